// round 2
// baseline (speedup 1.0000x reference)
#include <cuda_runtime.h>
#include <math.h>

// Problem constants (fixed by setup_inputs)
#define TOTAL_N 32768
#define NB      64      // B graphs
#define NG      512     // nodes per graph
#define NV      64      // virtual nodes
#define NH      256     // hidden
#define NIN     128
#define NOUT    10

// ---------------- scratch (device globals; no allocs allowed) ----------------
__device__ __align__(16) float d_bufA[TOTAL_N * NH];   // h / hw2 / t1
__device__ __align__(16) float d_bufB[TOTAL_N * NH];   // hw / t
__device__ __align__(16) float d_bufC[TOTAL_N * NH];   // agg / g
__device__ __align__(16) float d_deg[TOTAL_N];
__device__ __align__(16) float d_proto[NB * NH];
__device__ __align__(16) float d_pn[NB];
__device__ __align__(16) float d_att[TOTAL_N];
__device__ __align__(16) float d_mwn[NB * NG * NV];
__device__ __align__(16) float d_vn[NB * NV * NH];
__device__ __align__(16) float d_vn1[NB * NV * NH];
__device__ __align__(16) float d_gf[NB * NH];
__device__ __align__(16) float d_gf1[NB * NH];

// ---------------- generic tiled SGEMM: C = act(A[M,K] @ W[K,N] + bias) -------
// BM=BN=64, BK=16, 256 threads, 4x4 per thread. M%64==0, N%64==0, K%16==0.
template<bool RELU, bool BIAS>
__global__ void __launch_bounds__(256) sgemm64(
    const float* __restrict__ A, const float* __restrict__ W,
    const float* __restrict__ bias, float* __restrict__ C,
    int M, int K, int Nc)
{
    __shared__ __align__(16) float As[16][68];   // padded: avoid 4-way STS conflicts
    __shared__ __align__(16) float Bs[16][64];

    const int m0 = blockIdx.y * 64;
    const int n0 = blockIdx.x * 64;
    const int tid = threadIdx.x;
    const int tx = tid & 15;           // 0..15 -> 4 output cols
    const int ty = tid >> 4;           // 0..15 -> 4 output rows

    // A-tile loader: one float4 per thread (64 rows x 16 k)
    const int la_m = tid >> 2;
    const int la_k = (tid & 3) * 4;
    // B-tile loader: one float4 per thread (16 k x 64 n)
    const int lb_k = tid >> 4;
    const int lb_n = (tid & 15) * 4;

    const float* Aptr = A + (long long)(m0 + la_m) * K + la_k;
    const float* Wptr = W + (long long)lb_k * Nc + n0 + lb_n;

    float acc[4][4] = {};

    for (int k0 = 0; k0 < K; k0 += 16) {
        float4 av = *(const float4*)(Aptr + k0);
        As[la_k + 0][la_m] = av.x;
        As[la_k + 1][la_m] = av.y;
        As[la_k + 2][la_m] = av.z;
        As[la_k + 3][la_m] = av.w;
        *(float4*)&Bs[lb_k][lb_n] = *(const float4*)(Wptr + (long long)k0 * Nc);
        __syncthreads();
        #pragma unroll
        for (int k = 0; k < 16; k++) {
            float4 a4 = *(const float4*)&As[k][ty * 4];
            float4 b4 = *(const float4*)&Bs[k][tx * 4];
            float a[4] = {a4.x, a4.y, a4.z, a4.w};
            float b[4] = {b4.x, b4.y, b4.z, b4.w};
            #pragma unroll
            for (int i = 0; i < 4; i++)
                #pragma unroll
                for (int j = 0; j < 4; j++)
                    acc[i][j] += a[i] * b[j];
        }
        __syncthreads();
    }

    float bv[4] = {0.f, 0.f, 0.f, 0.f};
    if (BIAS) {
        float4 b4 = *(const float4*)&bias[n0 + tx * 4];
        bv[0] = b4.x; bv[1] = b4.y; bv[2] = b4.z; bv[3] = b4.w;
    }
    #pragma unroll
    for (int i = 0; i < 4; i++) {
        int m = m0 + ty * 4 + i;
        float4 r;
        float v0 = acc[i][0] + bv[0];
        float v1 = acc[i][1] + bv[1];
        float v2 = acc[i][2] + bv[2];
        float v3 = acc[i][3] + bv[3];
        if (RELU) {
            v0 = fmaxf(v0, 0.f); v1 = fmaxf(v1, 0.f);
            v2 = fmaxf(v2, 0.f); v3 = fmaxf(v3, 0.f);
        }
        r.x = v0; r.y = v1; r.z = v2; r.w = v3;
        *(float4*)&C[(long long)m * Nc + n0 + tx * 4] = r;
    }
}

// ---------------- init: zero agg, deg = 1 (self-loop) ------------------------
__global__ void init_kernel()
{
    int i = blockIdx.x * blockDim.x + threadIdx.x;
    int stride = gridDim.x * blockDim.x;
    for (int idx = i; idx < TOTAL_N * NH; idx += stride) d_bufC[idx] = 0.f;
    for (int idx = i; idx < TOTAL_N; idx += stride) d_deg[idx] = 1.f;
}

// ---------------- degree accumulation ----------------------------------------
__global__ void deg_kernel(const int* __restrict__ dst, int E)
{
    int i = blockIdx.x * blockDim.x + threadIdx.x;
    if (i < E) atomicAdd(&d_deg[dst[i]], 1.0f);
}

// ---------------- hw2 = hw * rsqrt(deg[row]) ---------------------------------
__global__ void scale_kernel()
{
    int i = blockIdx.x * blockDim.x + threadIdx.x;
    int stride = gridDim.x * blockDim.x;
    for (int idx = i; idx < TOTAL_N * NH; idx += stride) {
        int n = idx >> 8;
        d_bufA[idx] = d_bufB[idx] * rsqrtf(d_deg[n]);
    }
}

// ---------------- edge scatter: agg[dst] += hw2[src] -------------------------
// 64 threads per edge, float4 gather + 4 scalar atomics each.
__global__ void __launch_bounds__(256) scatter_kernel(
    const int* __restrict__ src, const int* __restrict__ dst, int E)
{
    int eb = blockIdx.x * 4 + (threadIdx.x >> 6);
    int lane = threadIdx.x & 63;
    if (eb >= E) return;
    int s = __ldg(&src[eb]);
    int d = __ldg(&dst[eb]);
    float4 v = *(const float4*)&d_bufA[(long long)s * NH + lane * 4];
    float* o = &d_bufC[(long long)d * NH + lane * 4];
    atomicAdd(o + 0, v.x);
    atomicAdd(o + 1, v.y);
    atomicAdd(o + 2, v.z);
    atomicAdd(o + 3, v.w);
}

// ---------------- g = relu(dinv*agg + hw/deg + b_gcn) ------------------------
__global__ void gcn_post_kernel(const float* __restrict__ b_gcn)
{
    int i = blockIdx.x * blockDim.x + threadIdx.x;
    int stride = gridDim.x * blockDim.x;
    for (int idx = i; idx < TOTAL_N * NH; idx += stride) {
        int n = idx >> 8;
        int h = idx & 255;
        float dg = d_deg[n];
        float val = rsqrtf(dg) * d_bufC[idx] + d_bufB[idx] / dg + b_gcn[h];
        d_bufC[idx] = fmaxf(val, 0.f);
    }
}

// ---------------- proto = mean_n t, pn = max(||proto||, eps) -----------------
__global__ void proto_kernel(const float* __restrict__ t)
{
    int b = blockIdx.x;
    int h = threadIdx.x;  // 256
    float s = 0.f;
    const float* tb = t + (long long)b * NG * NH + h;
    for (int n = 0; n < NG; n++) s += tb[(long long)n * NH];
    float p = s * (1.0f / NG);
    d_proto[b * NH + h] = p;
    __shared__ float red[256];
    red[h] = p * p;
    __syncthreads();
    for (int st = 128; st > 0; st >>= 1) {
        if (h < st) red[h] += red[h + st];
        __syncthreads();
    }
    if (h == 0) d_pn[b] = fmaxf(sqrtf(red[0]), 1e-8f);
}

// ---------------- att[node] = 0.5*(1 + cos(t[node], proto[b])) ---------------
__global__ void att_kernel(const float* __restrict__ t)
{
    int warp = threadIdx.x >> 5;
    int lane = threadIdx.x & 31;
    int node = blockIdx.x * 8 + warp;
    int b = node >> 9;  // /512
    const float* tr = t + (long long)node * NH;
    const float* pr = d_proto + b * NH;
    float dot = 0.f, sq = 0.f;
    #pragma unroll
    for (int i = lane; i < NH; i += 32) {
        float tv = tr[i];
        dot += tv * pr[i];
        sq += tv * tv;
    }
    #pragma unroll
    for (int o = 16; o; o >>= 1) {
        dot += __shfl_xor_sync(0xffffffffu, dot, o);
        sq  += __shfl_xor_sync(0xffffffffu, sq, o);
    }
    if (lane == 0) {
        float tn = fmaxf(sqrtf(sq), 1e-8f);
        float sim = dot / (tn * d_pn[b]);
        d_att[node] = 0.5f * (1.0f + sim);
    }
}

// ---------------- mwn row-normalized weighted edge weights -------------------
__global__ void mwn_kernel(const float* __restrict__ ew)
{
    int warp = threadIdx.x >> 5;
    int lane = threadIdx.x & 31;
    int row = blockIdx.x * 8 + warp;  // b*NG + n
    const float* e = ew + (long long)row * NV;
    float e0 = e[lane];
    float e1 = e[lane + 32];
    float s = e0 + e1;
    #pragma unroll
    for (int o = 16; o; o >>= 1) s += __shfl_xor_sync(0xffffffffu, s, o);
    float a = d_att[row];
    float rs = s * a;
    float inv = a / ((rs == 0.0f) ? 1.0f : rs);
    d_mwn[(long long)row * NV + lane]      = e0 * inv;
    d_mwn[(long long)row * NV + lane + 32] = e1 * inv;
}

// ---------------- vn[b] = mwn[b]^T (V x N) @ g[b] (N x H) --------------------
// one block per graph, 256 threads, 8x8 outputs per thread, K tiled by 32
__global__ void __launch_bounds__(256) vn_einsum(const float* __restrict__ g)
{
    int b = blockIdx.x;
    __shared__ __align__(16) float Ms[32][64];
    __shared__ __align__(16) float Gs[32][256];
    int tid = threadIdx.x;
    int tx = tid & 31;   // h block: 8 cols each
    int ty = tid >> 5;   // v block: 8 rows each
    float acc[8][8] = {};
    const float* mb = d_mwn + (long long)b * NG * NV;
    const float* gb = g + (long long)b * NG * NH;

    for (int k0 = 0; k0 < NG; k0 += 32) {
        #pragma unroll
        for (int it = 0; it < 2; it++) {
            int idx = tid + it * 256;
            int nl = idx >> 4;
            int v4 = (idx & 15) * 4;
            *(float4*)&Ms[nl][v4] = *(const float4*)&mb[(long long)(k0 + nl) * NV + v4];
        }
        #pragma unroll
        for (int it = 0; it < 8; it++) {
            int idx = tid + it * 256;
            int nl = idx >> 6;
            int h4 = (idx & 63) * 4;
            *(float4*)&Gs[nl][h4] = *(const float4*)&gb[(long long)(k0 + nl) * NH + h4];
        }
        __syncthreads();
        #pragma unroll 4
        for (int k = 0; k < 32; k++) {
            float av[8], gv[8];
            *(float4*)&av[0] = *(const float4*)&Ms[k][ty * 8];
            *(float4*)&av[4] = *(const float4*)&Ms[k][ty * 8 + 4];
            *(float4*)&gv[0] = *(const float4*)&Gs[k][tx * 8];
            *(float4*)&gv[4] = *(const float4*)&Gs[k][tx * 8 + 4];
            #pragma unroll
            for (int i = 0; i < 8; i++)
                #pragma unroll
                for (int j = 0; j < 8; j++)
                    acc[i][j] += av[i] * gv[j];
        }
        __syncthreads();
    }
    float* vb = d_vn + (long long)b * NV * NH;
    #pragma unroll
    for (int i = 0; i < 8; i++) {
        int v = ty * 8 + i;
        #pragma unroll
        for (int j4 = 0; j4 < 8; j4 += 4) {
            float4 r;
            r.x = acc[i][j4 + 0]; r.y = acc[i][j4 + 1];
            r.z = acc[i][j4 + 2]; r.w = acc[i][j4 + 3];
            *(float4*)&vb[(long long)v * NH + tx * 8 + j4] = r;
        }
    }
}

// ---------------- gf = mean_v vn2 --------------------------------------------
__global__ void gf_kernel(const float* __restrict__ vn2)
{
    int b = blockIdx.x;
    int h = threadIdx.x;
    float s = 0.f;
    for (int v = 0; v < NV; v++) s += vn2[((long long)b * NV + v) * NH + h];
    d_gf[b * NH + h] = s * (1.0f / NV);
}

// ---------------- out = gf1 @ mW2 + mb2 --------------------------------------
__global__ void out_kernel(const float* __restrict__ mW2,
                           const float* __restrict__ mb2,
                           float* __restrict__ out)
{
    int b = blockIdx.x;
    int w = threadIdx.x >> 5;   // output idx 0..9 (blockDim = 320)
    int lane = threadIdx.x & 31;
    if (w >= NOUT) return;
    const float* gr = d_gf1 + b * NH;
    float s = 0.f;
    #pragma unroll
    for (int i = lane; i < NH; i += 32) s += gr[i] * mW2[i * NOUT + w];
    #pragma unroll
    for (int o = 16; o; o >>= 1) s += __shfl_xor_sync(0xffffffffu, s, o);
    if (lane == 0) out[b * NOUT + w] = s + mb2[w];
}

// =============================================================================
extern "C" void kernel_launch(void* const* d_in, const int* in_sizes, int n_in,
                              void* d_out, int out_size)
{
    const float* x      = (const float*)d_in[0];
    const int*   esrc   = (const int*)  d_in[1];
    const int*   edst   = (const int*)  d_in[2];
    const float* W_emb  = (const float*)d_in[3];
    const float* b_emb  = (const float*)d_in[4];
    const float* W_gcn  = (const float*)d_in[5];
    const float* b_gcn  = (const float*)d_in[6];
    const float* aW1    = (const float*)d_in[7];
    const float* ab1    = (const float*)d_in[8];
    const float* aW2    = (const float*)d_in[9];
    const float* ab2    = (const float*)d_in[10];
    const float* vW1    = (const float*)d_in[11];
    const float* vb1    = (const float*)d_in[12];
    const float* vW2    = (const float*)d_in[13];
    const float* vb2    = (const float*)d_in[14];
    const float* mW1    = (const float*)d_in[15];
    const float* mb1    = (const float*)d_in[16];
    const float* mW2    = (const float*)d_in[17];
    const float* mb2    = (const float*)d_in[18];
    const float* ew     = (const float*)d_in[19];
    const int E = in_sizes[1];

    float *bufA, *bufB, *bufC, *pvn, *pvn1, *pgf, *pgf1;
    cudaGetSymbolAddress((void**)&bufA, d_bufA);
    cudaGetSymbolAddress((void**)&bufB, d_bufB);
    cudaGetSymbolAddress((void**)&bufC, d_bufC);
    cudaGetSymbolAddress((void**)&pvn,  d_vn);
    cudaGetSymbolAddress((void**)&pvn1, d_vn1);
    cudaGetSymbolAddress((void**)&pgf,  d_gf);
    cudaGetSymbolAddress((void**)&pgf1, d_gf1);

    dim3 g_big(NH / 64, TOTAL_N / 64);   // (4, 512)
    dim3 g_vnm(NH / 64, (NB * NV) / 64); // (4, 64)
    dim3 g_gf(NH / 64, 1);               // (4, 1)

    // 1) h = x @ W_emb + b_emb                      -> bufA
    sgemm64<false, true><<<g_big, 256>>>(x, W_emb, b_emb, bufA, TOTAL_N, NIN, NH);
    // 2) hw = h @ W_gcn                              -> bufB
    sgemm64<false, false><<<g_big, 256>>>(bufA, W_gcn, nullptr, bufB, TOTAL_N, NH, NH);
    // 3) deg (self-loop init), zero agg
    init_kernel<<<4096, 256>>>();
    deg_kernel<<<(E + 255) / 256, 256>>>(edst, E);
    // 4) hw2 = hw * rsqrt(deg)                       -> bufA
    scale_kernel<<<4096, 256>>>();
    // 5) agg[dst] += hw2[src]                        -> bufC
    scatter_kernel<<<(E + 3) / 4, 256>>>(esrc, edst, E);
    // 6) g = relu(dinv*agg + hw/deg + b_gcn)         -> bufC (in place)
    gcn_post_kernel<<<4096, 256>>>(b_gcn);
    // 7) t1 = relu(g @ aW1 + ab1)                    -> bufA
    sgemm64<true, true><<<g_big, 256>>>(bufC, aW1, ab1, bufA, TOTAL_N, NH, NH);
    // 8) t = t1 @ aW2 + ab2                          -> bufB
    sgemm64<false, true><<<g_big, 256>>>(bufA, aW2, ab2, bufB, TOTAL_N, NH, NH);
    // 9) proto / pn / att / mwn
    proto_kernel<<<NB, 256>>>(bufB);
    att_kernel<<<TOTAL_N / 8, 256>>>(bufB);
    mwn_kernel<<<(NB * NG) / 8, 256>>>(ew);
    // 10) vn = einsum(bnv,bnh->bvh)                  -> d_vn
    vn_einsum<<<NB, 256>>>(bufC);
    // 11) vn1 = relu(vn @ vW1 + vb1); vn2 = vn1 @ vW2 + vb2 (into d_vn)
    sgemm64<true, true><<<g_vnm, 256>>>(pvn, vW1, vb1, pvn1, NB * NV, NH, NH);
    sgemm64<false, true><<<g_vnm, 256>>>(pvn1, vW2, vb2, pvn, NB * NV, NH, NH);
    // 12) gf = mean_v vn2; gf1 = relu(gf @ mW1 + mb1); out
    gf_kernel<<<NB, 256>>>(pvn);
    sgemm64<true, true><<<g_gf, 256>>>(pgf, mW1, mb1, pgf1, 64, NH, NH);
    out_kernel<<<NB, 320>>>(mW2, mb2, (float*)d_out);
}